// round 6
// baseline (speedup 1.0000x reference)
#include <cuda_runtime.h>
#include <cuda_bf16.h>
#include <math.h>
#include <cstdint>

#define NN   8192
#define EE   262144
#define HID  512
#define LAT  128

// ---------------- scratch (__device__ globals; no allocation) ----------------
__device__ float g_h0[NN * HID];                 // x @ W1
__device__ float g_h[NN * HID];                  // relu(agg(h0) + b1)
__device__ float g_dinv[NN];
__device__ int   g_deg[NN];
__device__ int   g_off[NN + 1];
__device__ int   g_cursor[NN];
__device__ int   g_src[EE];
__device__ __nv_bfloat16 g_zs[NN * 128];         // z hi-only bf16
__device__ __nv_bfloat16 g_xs[NN * 1024];        // x split: [:,0:512]=hi, [:,512:1024]=lo
__device__ __nv_bfloat16 g_aggs[NN * 1024];      // agg(h) split
__device__ __nv_bfloat16 g_w1s[512 * 1024];      // W1^T split: [n][k-hi | k-lo]
__device__ __nv_bfloat16 g_wmls[256 * 1024];     // [Wmu^T ; Wlv^T] split

__device__ __forceinline__ uint32_t smem_to_u32(const void* smem_ptr) {
    uint32_t addr;
    asm("{ .reg .u64 tmp; cvta.to.shared.u64 tmp, %1; cvt.u32.u64 %0, tmp; }"
        : "=r"(addr) : "l"(smem_ptr));
    return addr;
}

// ---------------- graph preprocessing ----------------
__global__ void zero_kernel() {
    int i = blockIdx.x * blockDim.x + threadIdx.x;
    if (i < NN) { g_deg[i] = 0; g_cursor[i] = 0; }
}

__global__ void count_kernel(const int* __restrict__ col) {
    int e = blockIdx.x * blockDim.x + threadIdx.x;
    if (e < EE) atomicAdd(&g_deg[col[e]], 1);
}

// warp-shuffle scan of g_deg -> g_off, plus dinv (single block, 1024 threads x 8)
__global__ void scan_kernel() {
    __shared__ int wtot[32];
    int t = threadIdx.x, lane = t & 31, w = t >> 5;
    int base = t * 8;
    int d[8], pre[8];
    int sum = 0;
    #pragma unroll
    for (int i = 0; i < 8; i++) { d[i] = g_deg[base + i]; pre[i] = sum; sum += d[i]; }
    int v = sum;
    #pragma unroll
    for (int off = 1; off < 32; off <<= 1) {
        int n = __shfl_up_sync(0xffffffffu, v, off);
        if (lane >= off) v += n;
    }
    if (lane == 31) wtot[w] = v;
    __syncthreads();
    if (w == 0) {
        int x = wtot[lane];
        int y = x;
        #pragma unroll
        for (int off = 1; off < 32; off <<= 1) {
            int n = __shfl_up_sync(0xffffffffu, y, off);
            if (lane >= off) y += n;
        }
        wtot[lane] = y - x;
    }
    __syncthreads();
    int excl = v - sum + wtot[w];
    #pragma unroll
    for (int i = 0; i < 8; i++) g_off[base + i] = excl + pre[i];
    #pragma unroll
    for (int i = 0; i < 8; i++) g_dinv[base + i] = rsqrtf((float)(d[i] + 1));
    if (t == 1023) g_off[NN] = excl + sum;
}

__global__ void fill_kernel(const int* __restrict__ row, const int* __restrict__ col) {
    int e = blockIdx.x * blockDim.x + threadIdx.x;
    if (e < EE) {
        int c = col[e];
        int pos = g_off[c] + atomicAdd(&g_cursor[c], 1);
        g_src[pos] = row[e];
    }
}

// ---------------- splits ----------------
__device__ __forceinline__ void split2(float v, __nv_bfloat16& hi, __nv_bfloat16& lo) {
    hi = __float2bfloat16(v);
    lo = __float2bfloat16(v - __bfloat162float(hi));
}

__global__ void split_x_kernel(const float* __restrict__ X, __nv_bfloat16* __restrict__ Xs) {
    int i = blockIdx.x * blockDim.x + threadIdx.x;
    int row = i >> 9, k = i & 511;
    __nv_bfloat16 hi, lo;
    split2(X[i], hi, lo);
    Xs[(size_t)row * 1024 + k] = hi;
    Xs[(size_t)row * 1024 + 512 + k] = lo;
}

// W [512,N] -> Ws [N, 512hi | 512lo] (transpose + split)
__global__ void wsplit_kernel(const float* __restrict__ W, __nv_bfloat16* __restrict__ Ws, int N) {
    int i = blockIdx.x * blockDim.x + threadIdx.x;
    int k = i / N, n = i - k * N;
    if (k >= 512) return;
    __nv_bfloat16 hi, lo;
    split2(W[i], hi, lo);
    Ws[(size_t)n * 1024 + k] = hi;
    Ws[(size_t)n * 1024 + 512 + k] = lo;
}

// ---------------- aggregation ----------------
__global__ void aggregate_kernel(const float* __restrict__ H,
                                 const float* __restrict__ bias,
                                 float* __restrict__ out) {
    int node = blockIdx.x;
    int f = threadIdx.x * 4;
    float di = g_dinv[node];
    int s0 = g_off[node], s1 = g_off[node + 1];
    float4 acc = make_float4(0.f, 0.f, 0.f, 0.f);
    for (int e = s0; e < s1; e++) {
        int s = g_src[e];
        float w = g_dinv[s];
        float4 v = *(const float4*)&H[(size_t)s * HID + f];
        acc.x += w * v.x; acc.y += w * v.y; acc.z += w * v.z; acc.w += w * v.w;
    }
    float4 hv = *(const float4*)&H[(size_t)node * HID + f];
    float4 b = *(const float4*)&bias[f];
    float4 r;
    r.x = fmaxf(di * acc.x + di * di * hv.x + b.x, 0.f);
    r.y = fmaxf(di * acc.y + di * di * hv.y + b.y, 0.f);
    r.z = fmaxf(di * acc.z + di * di * hv.z + b.z, 0.f);
    r.w = fmaxf(di * acc.w + di * di * hv.w + b.w, 0.f);
    *(float4*)&out[(size_t)node * HID + f] = r;
}

// pass 2: aggregate + emit bf16 split rows directly
__global__ void aggregate_split_kernel(const float* __restrict__ H,
                                       __nv_bfloat16* __restrict__ outs) {
    int node = blockIdx.x;
    int f = threadIdx.x * 4;
    float di = g_dinv[node];
    int s0 = g_off[node], s1 = g_off[node + 1];
    float4 acc = make_float4(0.f, 0.f, 0.f, 0.f);
    for (int e = s0; e < s1; e++) {
        int s = g_src[e];
        float w = g_dinv[s];
        float4 v = *(const float4*)&H[(size_t)s * HID + f];
        acc.x += w * v.x; acc.y += w * v.y; acc.z += w * v.z; acc.w += w * v.w;
    }
    float4 hv = *(const float4*)&H[(size_t)node * HID + f];
    float r[4];
    r[0] = di * acc.x + di * di * hv.x;
    r[1] = di * acc.y + di * di * hv.y;
    r[2] = di * acc.z + di * di * hv.z;
    r[3] = di * acc.w + di * di * hv.w;
    size_t rb = (size_t)node * 1024 + f;
    #pragma unroll
    for (int j = 0; j < 4; j++) {
        __nv_bfloat16 hi, lo;
        split2(r[j], hi, lo);
        outs[rb + j] = hi;
        outs[rb + 512 + j] = lo;
    }
}

// ---------------- MMA primitives ----------------
__device__ __forceinline__ void ldsm_x4(uint32_t& r0, uint32_t& r1, uint32_t& r2, uint32_t& r3,
                                        uint32_t addr) {
    asm volatile("ldmatrix.sync.aligned.m8n8.x4.shared.b16 {%0,%1,%2,%3}, [%4];"
                 : "=r"(r0), "=r"(r1), "=r"(r2), "=r"(r3) : "r"(addr));
}

__device__ __forceinline__ void mma_bf16(float* c, const uint32_t* a, const uint32_t* b) {
    asm volatile(
        "mma.sync.aligned.m16n8k16.row.col.f32.bf16.bf16.f32 "
        "{%0,%1,%2,%3}, {%4,%5,%6,%7}, {%8,%9}, {%0,%1,%2,%3};"
        : "+f"(c[0]), "+f"(c[1]), "+f"(c[2]), "+f"(c[3])
        : "r"(a[0]), "r"(a[1]), "r"(a[2]), "r"(a[3]), "r"(b[0]), "r"(b[1]));
}

// ---------------- MMA GEMM (layer GEMMs): C = A @ B^T ----------------
// PHASES==3: split-GEMM hi*hi + hi*lo + lo*hi over [hi|lo] storage (row stride 2*KPART).
// MODE 0: C0 store (ld 512). MODE 2: +bias; gc<128 -> mu(C0)+zdup(C1)+zs-hi; gc>=128 -> lv(C2).
template<int KPART, int PHASES, int MODE>
__global__ __launch_bounds__(256) void mma_gemm(
    const __nv_bfloat16* __restrict__ A, const __nv_bfloat16* __restrict__ B,
    float* __restrict__ C0, float* __restrict__ C1, float* __restrict__ C2,
    const float* __restrict__ bias0, const float* __restrict__ bias1,
    __nv_bfloat16* __restrict__ zso) {
    constexpr int RS = (PHASES == 3 ? 2 : 1) * KPART;
    constexpr int CPK = KPART / 64;
    constexpr int NSTEP = PHASES * CPK;

    __shared__ __nv_bfloat16 As[128 * 64];
    __shared__ __nv_bfloat16 Bs[128 * 64];
    int tid = threadIdx.x;
    int wid = tid >> 5;
    int lane = tid & 31;
    int wm = wid & 3;
    int wn = wid >> 2;

    const __nv_bfloat16* Abase = A + (size_t)(blockIdx.y * 128) * RS;
    const __nv_bfloat16* Bbase = B + (size_t)(blockIdx.x * 128) * RS;
    uint32_t as_u = smem_to_u32(As);
    uint32_t bs_u = smem_to_u32(Bs);

    float acc[2][8][4] = {};

    for (int step = 0; step < NSTEP; step++) {
        int p = step / CPK;
        int kk = step % CPK;
        int aoff = (PHASES == 3 && p == 2) ? KPART : 0;
        int boff = (PHASES == 3 && p == 1) ? KPART : 0;
        #pragma unroll
        for (int i = 0; i < 4; i++) {
            int cid = tid + i * 256;
            int row = cid >> 3;
            int ch = cid & 7;
            int sw = (ch ^ (row & 7)) * 8;
            *(float4*)&As[row * 64 + sw] =
                *(const float4*)&Abase[(size_t)row * RS + aoff + kk * 64 + ch * 8];
            *(float4*)&Bs[row * 64 + sw] =
                *(const float4*)&Bbase[(size_t)row * RS + boff + kk * 64 + ch * 8];
        }
        __syncthreads();

        #pragma unroll
        for (int ks = 0; ks < 4; ks++) {
            uint32_t a[2][4];
            #pragma unroll
            for (int mt = 0; mt < 2; mt++) {
                int row = wm * 32 + mt * 16 + (lane & 15);
                int ch = ks * 2 + (lane >> 4);
                uint32_t addr = as_u + row * 128 + ((ch ^ (row & 7)) << 4);
                ldsm_x4(a[mt][0], a[mt][1], a[mt][2], a[mt][3], addr);
            }
            uint32_t b[8][2];
            #pragma unroll
            for (int q = 0; q < 4; q++) {
                int grp = lane >> 3;
                int nrow = wn * 64 + q * 16 + ((grp >> 1) << 3) + (lane & 7);
                int ch = ks * 2 + (grp & 1);
                uint32_t addr = bs_u + nrow * 128 + ((ch ^ (nrow & 7)) << 4);
                ldsm_x4(b[q * 2][0], b[q * 2][1], b[q * 2 + 1][0], b[q * 2 + 1][1], addr);
            }
            #pragma unroll
            for (int mt = 0; mt < 2; mt++)
                #pragma unroll
                for (int nt = 0; nt < 8; nt++)
                    mma_bf16(acc[mt][nt], a[mt], b[nt]);
        }
        __syncthreads();
    }

    int rbase = blockIdx.y * 128 + wm * 32 + (lane >> 2);
    int cloc = wn * 64 + (lane & 3) * 2;
    #pragma unroll
    for (int mt = 0; mt < 2; mt++) {
        #pragma unroll
        for (int nt = 0; nt < 8; nt++) {
            float* c = acc[mt][nt];
            int gc = blockIdx.x * 128 + cloc + nt * 8;
            #pragma unroll
            for (int rr = 0; rr < 2; rr++) {
                size_t row = (size_t)(rbase + mt * 16 + rr * 8);
                float v0 = c[rr * 2 + 0], v1 = c[rr * 2 + 1];
                if (MODE == 0) {
                    *(float2*)&C0[row * 512 + gc] = make_float2(v0, v1);
                } else {
                    if (gc < 128) {
                        v0 += bias0[gc]; v1 += bias0[gc + 1];
                        float2 v = make_float2(v0, v1);
                        *(float2*)&C0[row * LAT + gc] = v;
                        *(float2*)&C1[row * LAT + gc] = v;
                        zso[row * LAT + gc] = __float2bfloat16(v0);
                        zso[row * LAT + gc + 1] = __float2bfloat16(v1);
                    } else {
                        v0 += bias1[gc - 128]; v1 += bias1[gc - 127];
                        *(float2*)&C2[row * LAT + gc - 128] = make_float2(v0, v1);
                    }
                }
            }
        }
    }
}

// ---------------- symmetric zzt: A_pred = sigmoid(Z @ Z^T), upper-tri tiles only ----------------
// grid = 2080 (= 64*65/2). Tile (ti,tj), ti<=tj. Off-diagonal: also write transposed copy
// via SMEM staging (width 65 -> conflict-free column reads).
#define TTILES 64

__global__ __launch_bounds__(256) void zzt_sym_kernel(const __nv_bfloat16* __restrict__ Zs,
                                                      float* __restrict__ out) {
    __shared__ union {
        __nv_bfloat16 tiles[2 * 128 * 64];
        float stage[128 * 65];
    } su;
    __nv_bfloat16* As = su.tiles;
    __nv_bfloat16* Bs = su.tiles + 128 * 64;

    // triangular decode: b -> (ti, tj) with ti <= tj
    int b = blockIdx.x;
    float T5 = TTILES + 0.5f;
    int ti = (int)(T5 - sqrtf(T5 * T5 - 2.0f * (float)b));
    // start(ti) = ti*T - ti*(ti-1)/2
    #define TSTART(r) ((r) * TTILES - (r) * ((r) - 1) / 2)
    while (TSTART(ti + 1) <= b) ti++;
    while (TSTART(ti) > b) ti--;
    int tj = ti + (b - TSTART(ti));
    #undef TSTART

    int tid = threadIdx.x;
    int wid = tid >> 5;
    int lane = tid & 31;
    int wm = wid & 3;
    int wn = wid >> 2;

    const __nv_bfloat16* Abase = Zs + (size_t)(ti * 128) * 128;
    const __nv_bfloat16* Bbase = Zs + (size_t)(tj * 128) * 128;
    uint32_t as_u = smem_to_u32(As);
    uint32_t bs_u = smem_to_u32(Bs);

    float acc[2][8][4] = {};

    for (int kk = 0; kk < 2; kk++) {
        #pragma unroll
        for (int i = 0; i < 4; i++) {
            int cid = tid + i * 256;
            int row = cid >> 3;
            int ch = cid & 7;
            int sw = (ch ^ (row & 7)) * 8;
            *(float4*)&As[row * 64 + sw] =
                *(const float4*)&Abase[(size_t)row * 128 + kk * 64 + ch * 8];
            *(float4*)&Bs[row * 64 + sw] =
                *(const float4*)&Bbase[(size_t)row * 128 + kk * 64 + ch * 8];
        }
        __syncthreads();

        #pragma unroll
        for (int ks = 0; ks < 4; ks++) {
            uint32_t a[2][4];
            #pragma unroll
            for (int mt = 0; mt < 2; mt++) {
                int row = wm * 32 + mt * 16 + (lane & 15);
                int ch = ks * 2 + (lane >> 4);
                uint32_t addr = as_u + row * 128 + ((ch ^ (row & 7)) << 4);
                ldsm_x4(a[mt][0], a[mt][1], a[mt][2], a[mt][3], addr);
            }
            uint32_t bfr[8][2];
            #pragma unroll
            for (int q = 0; q < 4; q++) {
                int grp = lane >> 3;
                int nrow = wn * 64 + q * 16 + ((grp >> 1) << 3) + (lane & 7);
                int ch = ks * 2 + (grp & 1);
                uint32_t addr = bs_u + nrow * 128 + ((ch ^ (nrow & 7)) << 4);
                ldsm_x4(bfr[q * 2][0], bfr[q * 2][1], bfr[q * 2 + 1][0], bfr[q * 2 + 1][1], addr);
            }
            #pragma unroll
            for (int mt = 0; mt < 2; mt++)
                #pragma unroll
                for (int nt = 0; nt < 8; nt++)
                    mma_bf16(acc[mt][nt], a[mt], bfr[nt]);
        }
        __syncthreads();
    }

    // sigmoid in place
    #pragma unroll
    for (int mt = 0; mt < 2; mt++)
        #pragma unroll
        for (int nt = 0; nt < 8; nt++)
            #pragma unroll
            for (int q = 0; q < 4; q++)
                acc[mt][nt][q] = 1.f / (1.f + __expf(-acc[mt][nt][q]));

    // direct store: out[ti*128 + r][tj*128 + c]
    int rloc = wm * 32 + (lane >> 2);
    int cloc = wn * 64 + (lane & 3) * 2;
    #pragma unroll
    for (int mt = 0; mt < 2; mt++) {
        #pragma unroll
        for (int nt = 0; nt < 8; nt++) {
            float* c = acc[mt][nt];
            int gc = tj * 128 + cloc + nt * 8;
            #pragma unroll
            for (int rr = 0; rr < 2; rr++) {
                size_t row = (size_t)(ti * 128 + rloc + mt * 16 + rr * 8);
                *(float2*)&out[row * NN + gc] = make_float2(c[rr * 2 + 0], c[rr * 2 + 1]);
            }
        }
    }

    // transposed store: out[tj*128 + c][ti*128 + r], staged half-tile at a time
    if (ti != tj) {
        #pragma unroll
        for (int h = 0; h < 2; h++) {
            __syncthreads();                // stage buffer free (tiles dead / prev round done)
            if (wn == h) {
                #pragma unroll
                for (int mt = 0; mt < 2; mt++) {
                    #pragma unroll
                    for (int nt = 0; nt < 8; nt++) {
                        float* c = acc[mt][nt];
                        int cl = (lane & 3) * 2 + nt * 8;   // 0..63 within half
                        #pragma unroll
                        for (int rr = 0; rr < 2; rr++) {
                            int lr = rloc + mt * 16 + rr * 8;
                            su.stage[lr * 65 + cl]     = c[rr * 2 + 0];
                            su.stage[lr * 65 + cl + 1] = c[rr * 2 + 1];
                        }
                    }
                }
            }
            __syncthreads();
            // write transposed rows h*64 .. h*64+63 (each = orig column)
            int trl = tid >> 2;             // 0..63
            int seg = tid & 3;              // 32 orig-rows each
            size_t grow = (size_t)(tj * 128 + h * 64 + trl);
            size_t obase = grow * NN + ti * 128 + seg * 32;
            #pragma unroll
            for (int q = 0; q < 8; q++) {
                int r0 = seg * 32 + q * 4;
                float4 v;
                v.x = su.stage[(r0 + 0) * 65 + trl];
                v.y = su.stage[(r0 + 1) * 65 + trl];
                v.z = su.stage[(r0 + 2) * 65 + trl];
                v.w = su.stage[(r0 + 3) * 65 + trl];
                *(float4*)&out[obase + q * 4] = v;
            }
        }
    }
}

// ---------------- launch ----------------
extern "C" void kernel_launch(void* const* d_in, const int* in_sizes, int n_in,
                              void* d_out, int out_size) {
    const int*   edge = (const int*)d_in[0];
    const float* x    = (const float*)d_in[1];
    const float* W1   = (const float*)d_in[2];
    const float* b1   = (const float*)d_in[3];
    const float* Wmu  = (const float*)d_in[4];
    const float* bmu  = (const float*)d_in[5];
    const float* Wlv  = (const float*)d_in[6];
    const float* blv  = (const float*)d_in[7];

    const int* row = edge;
    const int* col = edge + EE;

    float* out     = (float*)d_out;
    float* A_pred  = out;
    float* mu_out  = out + (size_t)NN * NN;
    float* lv_out  = mu_out + (size_t)NN * LAT;
    float* z_out   = lv_out + (size_t)NN * LAT;

    float* h0;   cudaGetSymbolAddress((void**)&h0,   g_h0);
    float* h;    cudaGetSymbolAddress((void**)&h,    g_h);
    __nv_bfloat16* zs;   cudaGetSymbolAddress((void**)&zs,   g_zs);
    __nv_bfloat16* xs;   cudaGetSymbolAddress((void**)&xs,   g_xs);
    __nv_bfloat16* aggs; cudaGetSymbolAddress((void**)&aggs, g_aggs);
    __nv_bfloat16* w1s;  cudaGetSymbolAddress((void**)&w1s,  g_w1s);
    __nv_bfloat16* wmls; cudaGetSymbolAddress((void**)&wmls, g_wmls);

    // graph preprocessing
    zero_kernel<<<(NN + 255) / 256, 256>>>();
    count_kernel<<<(EE + 255) / 256, 256>>>(col);
    scan_kernel<<<1, 1024>>>();
    fill_kernel<<<(EE + 255) / 256, 256>>>(row, col);

    // splits
    split_x_kernel<<<(NN * 512) / 256, 256>>>(x, xs);
    wsplit_kernel<<<(512 * 512) / 256, 256>>>(W1, w1s, 512);
    wsplit_kernel<<<(512 * 128) / 256, 256>>>(Wmu, wmls, 128);
    wsplit_kernel<<<(512 * 128) / 256, 256>>>(Wlv, wmls + 128 * 1024, 128);

    // layer 1: h0 = x @ W1 (3-phase split GEMM); h = relu(agg(h0) + b1)
    mma_gemm<512, 3, 0><<<dim3(4, 64), 256>>>(xs, w1s, h0, nullptr, nullptr,
                                              nullptr, nullptr, nullptr);
    aggregate_kernel<<<NN, 128>>>(h0, b1, h);

    // layer 2: aggs = split(agg(h)); [mu|lv] = aggs @ [Wmu|Wlv] + bias (emits zs hi)
    aggregate_split_kernel<<<NN, 128>>>(h, aggs);
    mma_gemm<512, 3, 2><<<dim3(2, 64), 256>>>(aggs, wmls, mu_out, z_out, lv_out,
                                              bmu, blv, zs);

    // decode: A_pred = sigmoid(z z^T), symmetric upper-tri tiles + transposed copy
    zzt_sym_kernel<<<(TTILES * (TTILES + 1)) / 2, 256>>>(zs, A_pred);
}